// round 1
// baseline (speedup 1.0000x reference)
#include <cuda_runtime.h>
#include <cstdint>

#define BB 8
#define TT 2048
#define EE 1024
#define DD 128

// Scratch for projected Q/K/V (no cudaMalloc allowed -> __device__ globals)
__device__ float g_q[BB * TT * DD];
__device__ float g_k[BB * TT * DD];
__device__ float g_v[BB * TT * DD];

// ---------------------------------------------------------------------------
// Projection: X[16384,1024] @ W[1024,128] for each of Wk,Wq,Wv (blockIdx.y)
// 128x128 tile, BK=16, 256 threads, 8x8 microtile.
// ---------------------------------------------------------------------------
__global__ __launch_bounds__(256, 1) void proj_kernel(
    const float* __restrict__ X,
    const float* __restrict__ Wk,
    const float* __restrict__ Wq,
    const float* __restrict__ Wv) {
    __shared__ __align__(16) float As[16][132];  // [k][m] (transposed X tile)
    __shared__ __align__(16) float Bs[16][132];  // [k][d]

    const float* W;
    float* O;
    if (blockIdx.y == 0)      { W = Wk; O = g_k; }
    else if (blockIdx.y == 1) { W = Wq; O = g_q; }
    else                      { W = Wv; O = g_v; }

    const int tid = threadIdx.x;
    const int tr = tid >> 4;       // 0..15 -> rows 8*tr..8*tr+7
    const int tc = tid & 15;       // 0..15 -> cols 4*tc..+3 and 64+4*tc..+3
    const int m0 = blockIdx.x * 128;

    float acc[8][8];
#pragma unroll
    for (int i = 0; i < 8; i++)
#pragma unroll
        for (int j = 0; j < 8; j++) acc[i][j] = 0.f;

    for (int e0 = 0; e0 < EE; e0 += 16) {
        // Load X tile (128 x 16) transposed into As[k][m]
#pragma unroll
        for (int g = 0; g < 2; g++) {
            int idx = tid + 256 * g;          // 0..511
            int m = idx >> 2;                 // 0..127
            int q = idx & 3;                  // 0..3 (float4 within 16 cols)
            float4 xv = *(const float4*)(X + (size_t)(m0 + m) * EE + e0 + 4 * q);
            As[4 * q + 0][m] = xv.x;
            As[4 * q + 1][m] = xv.y;
            As[4 * q + 2][m] = xv.z;
            As[4 * q + 3][m] = xv.w;
        }
        // Load W tile (16 x 128) into Bs[k][d]
#pragma unroll
        for (int g = 0; g < 2; g++) {
            int idx = tid + 256 * g;          // 0..511
            int k = idx >> 5;                 // 0..15
            int q = idx & 31;                 // 0..31
            *(float4*)&Bs[k][4 * q] =
                *(const float4*)(W + (size_t)(e0 + k) * DD + 4 * q);
        }
        __syncthreads();

#pragma unroll
        for (int k = 0; k < 16; k++) {
            float4 a0 = *(const float4*)&As[k][8 * tr];
            float4 a1 = *(const float4*)&As[k][8 * tr + 4];
            float4 b0 = *(const float4*)&Bs[k][4 * tc];
            float4 b1 = *(const float4*)&Bs[k][64 + 4 * tc];
            float a[8] = {a0.x, a0.y, a0.z, a0.w, a1.x, a1.y, a1.z, a1.w};
            float b[8] = {b0.x, b0.y, b0.z, b0.w, b1.x, b1.y, b1.z, b1.w};
#pragma unroll
            for (int i = 0; i < 8; i++)
#pragma unroll
                for (int j = 0; j < 8; j++) acc[i][j] += a[i] * b[j];
        }
        __syncthreads();
    }

#pragma unroll
    for (int i = 0; i < 8; i++) {
        float4 o0 = make_float4(acc[i][0], acc[i][1], acc[i][2], acc[i][3]);
        float4 o1 = make_float4(acc[i][4], acc[i][5], acc[i][6], acc[i][7]);
        size_t row = (size_t)(m0 + 8 * tr + i) * DD;
        *(float4*)(O + row + 4 * tc) = o0;
        *(float4*)(O + row + 64 + 4 * tc) = o1;
    }
}

// ---------------------------------------------------------------------------
// Flash attention, causal. Br=Bc=64, 256 threads, dynamic smem ~114.8KB.
// ---------------------------------------------------------------------------
struct AttnSmem {
    float Qs[64][128];   // [row][d]           32 KB
    float Kt[128][68];   // [d][col] (padded)  34.8 KB
    float Vs[64][128];   // [col][d]           32 KB
    float Ps[64][64];    // S then P           16 KB
    float m_s[64];
    float l_s[64];
    float sc_s[64];
};

__global__ __launch_bounds__(256, 1) void attn_kernel(float* __restrict__ out) {
    extern __shared__ __align__(16) char smem_raw[];
    AttnSmem& S = *reinterpret_cast<AttnSmem*>(smem_raw);

    const int b = blockIdx.y;
    const int t_tile = (int)(gridDim.x - 1) - (int)blockIdx.x;  // big tiles first
    const int tq0 = t_tile * 64;
    const int tid = threadIdx.x;
    const int tr = tid >> 4;   // 0..15
    const int tc = tid & 15;   // 0..15
    const int r0 = 4 * tr;     // S/O rows owned by this thread
    const float SM_SCALE = 0.08838834764831845f;  // 1/sqrt(128)
    const float NEG_INF = __int_as_float(0xff800000);

    float o[4][8];
#pragma unroll
    for (int i = 0; i < 4; i++)
#pragma unroll
        for (int j = 0; j < 8; j++) o[i][j] = 0.f;

    // Load Q tile (64 x 128)
    const float* Qg = g_q + ((size_t)b * TT + tq0) * DD;
#pragma unroll
    for (int g = 0; g < 8; g++) {
        int idx = tid + 256 * g;      // 0..2047
        int m = idx >> 5;             // 0..63
        int q = idx & 31;             // 0..31
        *(float4*)&S.Qs[m][4 * q] = *(const float4*)(Qg + (size_t)m * DD + 4 * q);
    }
    if (tid < 64) {
        S.m_s[tid] = NEG_INF;
        S.l_s[tid] = 0.f;
    }

    for (int jt = 0; jt <= t_tile; jt++) {
        const int j0 = jt * 64;
        const float* Kg = g_k + ((size_t)b * TT + j0) * DD;
        const float* Vg = g_v + ((size_t)b * TT + j0) * DD;

        // K tile transposed: Kt[d][col]
#pragma unroll
        for (int g = 0; g < 8; g++) {
            int idx = tid + 256 * g;
            int q = idx >> 6;          // d-quad 0..31
            int m = idx & 63;          // col 0..63
            float4 kv = *(const float4*)(Kg + (size_t)m * DD + 4 * q);
            S.Kt[4 * q + 0][m] = kv.x;
            S.Kt[4 * q + 1][m] = kv.y;
            S.Kt[4 * q + 2][m] = kv.z;
            S.Kt[4 * q + 3][m] = kv.w;
        }
        // V tile direct
#pragma unroll
        for (int g = 0; g < 8; g++) {
            int idx = tid + 256 * g;
            int m = idx >> 5;
            int q = idx & 31;
            *(float4*)&S.Vs[m][4 * q] = *(const float4*)(Vg + (size_t)m * DD + 4 * q);
        }
        __syncthreads();

        // S = Q @ K^T (each thread: 4x4 at [r0..r0+3][4tc..4tc+3])
        float s[4][4];
#pragma unroll
        for (int i = 0; i < 4; i++)
#pragma unroll
            for (int j = 0; j < 4; j++) s[i][j] = 0.f;

#pragma unroll 4
        for (int kk = 0; kk < 128; kk += 4) {
            float4 kv0 = *(const float4*)&S.Kt[kk + 0][4 * tc];
            float4 kv1 = *(const float4*)&S.Kt[kk + 1][4 * tc];
            float4 kv2 = *(const float4*)&S.Kt[kk + 2][4 * tc];
            float4 kv3 = *(const float4*)&S.Kt[kk + 3][4 * tc];
#pragma unroll
            for (int i = 0; i < 4; i++) {
                float4 qv = *(const float4*)&S.Qs[r0 + i][kk];
                s[i][0] += qv.x * kv0.x; s[i][1] += qv.x * kv0.y;
                s[i][2] += qv.x * kv0.z; s[i][3] += qv.x * kv0.w;
                s[i][0] += qv.y * kv1.x; s[i][1] += qv.y * kv1.y;
                s[i][2] += qv.y * kv1.z; s[i][3] += qv.y * kv1.w;
                s[i][0] += qv.z * kv2.x; s[i][1] += qv.z * kv2.y;
                s[i][2] += qv.z * kv2.z; s[i][3] += qv.z * kv2.w;
                s[i][0] += qv.w * kv3.x; s[i][1] += qv.w * kv3.y;
                s[i][2] += qv.w * kv3.z; s[i][3] += qv.w * kv3.w;
            }
        }

        // Scale, causal mask (only on diagonal tile), store to Ps
        const bool diag = (jt == t_tile);
#pragma unroll
        for (int i = 0; i < 4; i++) {
            int r = r0 + i;
            float4 sv = make_float4(s[i][0] * SM_SCALE, s[i][1] * SM_SCALE,
                                    s[i][2] * SM_SCALE, s[i][3] * SM_SCALE);
            if (diag) {
                if (4 * tc + 0 > r) sv.x = NEG_INF;
                if (4 * tc + 1 > r) sv.y = NEG_INF;
                if (4 * tc + 2 > r) sv.z = NEG_INF;
                if (4 * tc + 3 > r) sv.w = NEG_INF;
            }
            *(float4*)&S.Ps[r][4 * tc] = sv;
        }
        __syncthreads();

        // Online softmax: 4 lanes per row, 16 cols each
        {
            int r = tid >> 2;
            int qu = tid & 3;
            float m_old = S.m_s[r];
            float l_old = S.l_s[r];
            float v[16];
#pragma unroll
            for (int g = 0; g < 4; g++) {
                float4 pv = *(const float4*)&S.Ps[r][16 * qu + 4 * g];
                v[4 * g + 0] = pv.x; v[4 * g + 1] = pv.y;
                v[4 * g + 2] = pv.z; v[4 * g + 3] = pv.w;
            }
            float mx = v[0];
#pragma unroll
            for (int k = 1; k < 16; k++) mx = fmaxf(mx, v[k]);
            mx = fmaxf(mx, __shfl_xor_sync(0xffffffffu, mx, 1));
            mx = fmaxf(mx, __shfl_xor_sync(0xffffffffu, mx, 2));
            float m_new = fmaxf(m_old, mx);
            float sum = 0.f;
#pragma unroll
            for (int k = 0; k < 16; k++) {
                float e = __expf(v[k] - m_new);
                v[k] = e;
                sum += e;
            }
            sum += __shfl_xor_sync(0xffffffffu, sum, 1);
            sum += __shfl_xor_sync(0xffffffffu, sum, 2);
#pragma unroll
            for (int g = 0; g < 4; g++) {
                float4 pv = make_float4(v[4 * g + 0], v[4 * g + 1],
                                        v[4 * g + 2], v[4 * g + 3]);
                *(float4*)&S.Ps[r][16 * qu + 4 * g] = pv;
            }
            if (qu == 0) {
                float sc = __expf(m_old - m_new);
                S.sc_s[r] = sc;
                S.l_s[r] = l_old * sc + sum;
                S.m_s[r] = m_new;
            }
        }
        __syncthreads();

        // O = O*scale + P @ V
        float scl[4];
#pragma unroll
        for (int i = 0; i < 4; i++) scl[i] = S.sc_s[r0 + i];
#pragma unroll
        for (int i = 0; i < 4; i++)
#pragma unroll
            for (int j = 0; j < 8; j++) o[i][j] *= scl[i];

#pragma unroll 2
        for (int jj = 0; jj < 64; jj += 4) {
            float4 p0 = *(const float4*)&S.Ps[r0 + 0][jj];
            float4 p1 = *(const float4*)&S.Ps[r0 + 1][jj];
            float4 p2 = *(const float4*)&S.Ps[r0 + 2][jj];
            float4 p3 = *(const float4*)&S.Ps[r0 + 3][jj];
            float pr[4][4] = {{p0.x, p0.y, p0.z, p0.w},
                              {p1.x, p1.y, p1.z, p1.w},
                              {p2.x, p2.y, p2.z, p2.w},
                              {p3.x, p3.y, p3.z, p3.w}};
#pragma unroll
            for (int t2 = 0; t2 < 4; t2++) {
                float4 v0 = *(const float4*)&S.Vs[jj + t2][4 * tc];
                float4 v1 = *(const float4*)&S.Vs[jj + t2][64 + 4 * tc];
#pragma unroll
                for (int i = 0; i < 4; i++) {
                    float pv = pr[i][t2];
                    o[i][0] += pv * v0.x; o[i][1] += pv * v0.y;
                    o[i][2] += pv * v0.z; o[i][3] += pv * v0.w;
                    o[i][4] += pv * v1.x; o[i][5] += pv * v1.y;
                    o[i][6] += pv * v1.z; o[i][7] += pv * v1.w;
                }
            }
        }
        __syncthreads();
    }

    // Normalize and write out
    float* Og = out + ((size_t)b * TT + tq0 + r0) * DD;
#pragma unroll
    for (int i = 0; i < 4; i++) {
        float inv = 1.0f / S.l_s[r0 + i];
        float4 o0 = make_float4(o[i][0] * inv, o[i][1] * inv,
                                o[i][2] * inv, o[i][3] * inv);
        float4 o1 = make_float4(o[i][4] * inv, o[i][5] * inv,
                                o[i][6] * inv, o[i][7] * inv);
        *(float4*)(Og + (size_t)i * DD + 4 * tc) = o0;
        *(float4*)(Og + (size_t)i * DD + 64 + 4 * tc) = o1;
    }
}

// ---------------------------------------------------------------------------
extern "C" void kernel_launch(void* const* d_in, const int* in_sizes, int n_in,
                              void* d_out, int out_size) {
    const float* x  = (const float*)d_in[0];
    const float* Wk = (const float*)d_in[1];
    const float* Wq = (const float*)d_in[2];
    const float* Wv = (const float*)d_in[3];
    float* out = (float*)d_out;

    // QKV projections: 16384x1024 @ 1024x128, one y-slice per weight
    dim3 pgrid(128, 3);
    proj_kernel<<<pgrid, 256>>>(x, Wk, Wq, Wv);

    // Flash attention
    cudaFuncSetAttribute(attn_kernel, cudaFuncAttributeMaxDynamicSharedMemorySize,
                         (int)sizeof(AttnSmem));
    dim3 agrid(32, 8);  // t tiles x batch
    attn_kernel<<<agrid, 256, sizeof(AttnSmem)>>>(out);
}

// round 2
// speedup vs baseline: 2.5331x; 2.5331x over previous
#include <cuda_runtime.h>
#include <cstdint>

#define BB 8
#define TT 2048
#define EE 1024
#define DD 128

// Scratch for projected Q/K/V (no cudaMalloc allowed -> __device__ globals)
__device__ float g_q[BB * TT * DD];
__device__ float g_k[BB * TT * DD];
__device__ float g_v[BB * TT * DD];

__device__ __forceinline__ uint32_t f2tf(float f) {
    uint32_t r;
    asm("cvt.rna.tf32.f32 %0, %1;" : "=r"(r) : "f"(f));
    return r;
}

// D += A*B, m16n8k8 tf32
__device__ __forceinline__ void mma8(float* d, const uint32_t* a, const uint32_t* b) {
    asm volatile(
        "mma.sync.aligned.m16n8k8.row.col.f32.tf32.tf32.f32 "
        "{%0,%1,%2,%3}, {%4,%5,%6,%7}, {%8,%9}, {%0,%1,%2,%3};"
        : "+f"(d[0]), "+f"(d[1]), "+f"(d[2]), "+f"(d[3])
        : "r"(a[0]), "r"(a[1]), "r"(a[2]), "r"(a[3]), "r"(b[0]), "r"(b[1]));
}

// ---------------------------------------------------------------------------
// Projection: X[16384,1024] @ W[1024,128], tf32 MMA. 128x128 tile, BK=32.
// 8 warps: warp_m = wid&1 (64 rows), warp_n = wid>>1 (32 cols).
// ---------------------------------------------------------------------------
__global__ __launch_bounds__(256) void proj_kernel(
    const float* __restrict__ X,
    const float* __restrict__ Wk,
    const float* __restrict__ Wq,
    const float* __restrict__ Wv) {
    __shared__ uint32_t As[128][36];   // [m][k], frag loads (4g+tig)%32 unique
    __shared__ uint32_t Bs[32][136];   // [k][n], frag loads (8tig+g)%32 unique

    const float* W;
    float* O;
    if (blockIdx.y == 0)      { W = Wk; O = g_k; }
    else if (blockIdx.y == 1) { W = Wq; O = g_q; }
    else                      { W = Wv; O = g_v; }

    const int tid = threadIdx.x;
    const int wid = tid >> 5, lane = tid & 31;
    const int group = lane >> 2, tig = lane & 3;
    const int wm = wid & 1, wn = wid >> 1;
    const int m0 = blockIdx.x * 128;

    const int xrow = tid >> 3, xq = tid & 7;     // +32g rows
    const int wrow = tid >> 5, wq = tid & 31;    // +8g rows

    float acc[4][4][4];
#pragma unroll
    for (int mt = 0; mt < 4; mt++)
#pragma unroll
        for (int nt = 0; nt < 4; nt++)
#pragma unroll
            for (int c = 0; c < 4; c++) acc[mt][nt][c] = 0.f;

    float4 xv[4], wv[4];
#pragma unroll
    for (int g = 0; g < 4; g++) {
        xv[g] = *(const float4*)(X + (size_t)(m0 + xrow + 32 * g) * EE + 4 * xq);
        wv[g] = *(const float4*)(W + (size_t)(wrow + 8 * g) * DD + 4 * wq);
    }

    for (int e0 = 0; e0 < EE; e0 += 32) {
#pragma unroll
        for (int g = 0; g < 4; g++) {
            uint4 xa = make_uint4(f2tf(xv[g].x), f2tf(xv[g].y), f2tf(xv[g].z), f2tf(xv[g].w));
            *(uint4*)&As[xrow + 32 * g][4 * xq] = xa;
            uint4 wa = make_uint4(f2tf(wv[g].x), f2tf(wv[g].y), f2tf(wv[g].z), f2tf(wv[g].w));
            *(uint4*)&Bs[wrow + 8 * g][4 * wq] = wa;
        }
        __syncthreads();

        if (e0 + 32 < EE) {
#pragma unroll
            for (int g = 0; g < 4; g++) {
                xv[g] = *(const float4*)(X + (size_t)(m0 + xrow + 32 * g) * EE + e0 + 32 + 4 * xq);
                wv[g] = *(const float4*)(W + (size_t)(e0 + 32 + wrow + 8 * g) * DD + 4 * wq);
            }
        }

#pragma unroll
        for (int kt = 0; kt < 4; kt++) {
            const int k0 = kt * 8;
            uint32_t a[4][4], b[4][2];
#pragma unroll
            for (int mt = 0; mt < 4; mt++) {
                int r = wm * 64 + mt * 16 + group;
                a[mt][0] = As[r][k0 + tig];
                a[mt][1] = As[r + 8][k0 + tig];
                a[mt][2] = As[r][k0 + tig + 4];
                a[mt][3] = As[r + 8][k0 + tig + 4];
            }
#pragma unroll
            for (int nt = 0; nt < 4; nt++) {
                int c = wn * 32 + nt * 8 + group;
                b[nt][0] = Bs[k0 + tig][c];
                b[nt][1] = Bs[k0 + tig + 4][c];
            }
#pragma unroll
            for (int mt = 0; mt < 4; mt++)
#pragma unroll
                for (int nt = 0; nt < 4; nt++) mma8(acc[mt][nt], a[mt], b[nt]);
        }
        __syncthreads();
    }

#pragma unroll
    for (int mt = 0; mt < 4; mt++) {
        int r = m0 + wm * 64 + mt * 16 + group;
#pragma unroll
        for (int nt = 0; nt < 4; nt++) {
            int c = wn * 32 + nt * 8 + 2 * tig;
            *(float2*)(O + (size_t)r * DD + c) = make_float2(acc[mt][nt][0], acc[mt][nt][1]);
            *(float2*)(O + (size_t)(r + 8) * DD + c) = make_float2(acc[mt][nt][2], acc[mt][nt][3]);
        }
    }
}

// ---------------------------------------------------------------------------
// Flash attention, causal, tf32 MMA. Br=Bc=64, 256 threads.
// Warps: wm = wid>>1 (16 rows each), wn = wid&1 (32 S-cols / 64 O-cols).
// ---------------------------------------------------------------------------
struct AttnSmem {
    uint32_t Qs[64][132];   // [row][d], pre-scaled, (4g+tig) unique
    uint32_t Ks[64][132];   // [key][d], (4g+tig) unique
    uint32_t Vs[64][136];   // [key][d], (8tig+g) unique
    uint32_t Ps[64][68];    // [row][key], (4g+tig) unique
    float m_s[64], l_s[64], sc_s[64];
    float redm[64][2], reds[64][2];
};

__global__ __launch_bounds__(256) void attn_kernel(float* __restrict__ out) {
    extern __shared__ __align__(16) char smem_raw[];
    AttnSmem& S = *reinterpret_cast<AttnSmem*>(smem_raw);

    const int b = blockIdx.y;
    const int t_tile = (int)(gridDim.x - 1) - (int)blockIdx.x;  // long rows first
    const int tq0 = t_tile * 64;
    const int tid = threadIdx.x;
    const int wid = tid >> 5, lane = tid & 31;
    const int group = lane >> 2, tig = lane & 3;
    const int wm = wid >> 1, wn = wid & 1;
    const int r0 = wm * 16 + group;               // local rows r0, r0+8
    const float SM_SCALE = 0.08838834764831845f;  // 1/sqrt(128)
    const float NEG_INF = __int_as_float(0xff800000);

    const int grow = tid >> 5, gq = tid & 31;     // tile-load mapping (+8g rows)

    float o[8][4];
#pragma unroll
    for (int nt = 0; nt < 8; nt++)
#pragma unroll
        for (int c = 0; c < 4; c++) o[nt][c] = 0.f;

    // Q tile (pre-scaled by 1/sqrt(D))
    const float* Qg = g_q + ((size_t)b * TT + tq0) * DD;
#pragma unroll
    for (int g = 0; g < 8; g++) {
        float4 qv = *(const float4*)(Qg + (size_t)(grow + 8 * g) * DD + 4 * gq);
        uint4 qa = make_uint4(f2tf(qv.x * SM_SCALE), f2tf(qv.y * SM_SCALE),
                              f2tf(qv.z * SM_SCALE), f2tf(qv.w * SM_SCALE));
        *(uint4*)&S.Qs[grow + 8 * g][4 * gq] = qa;
    }
    if (tid < 64) {
        S.m_s[tid] = NEG_INF;
        S.l_s[tid] = 0.f;
    }

    for (int jt = 0; jt <= t_tile; jt++) {
        const int j0 = jt * 64;
        const float* Kg = g_k + ((size_t)b * TT + j0) * DD;
        const float* Vg = g_v + ((size_t)b * TT + j0) * DD;

        __syncthreads();  // protect Ks/Vs/Ps reuse (and Qs/stats on iter 0)
#pragma unroll
        for (int g = 0; g < 8; g++) {
            float4 kv = *(const float4*)(Kg + (size_t)(grow + 8 * g) * DD + 4 * gq);
            *(uint4*)&S.Ks[grow + 8 * g][4 * gq] =
                make_uint4(f2tf(kv.x), f2tf(kv.y), f2tf(kv.z), f2tf(kv.w));
            float4 vv = *(const float4*)(Vg + (size_t)(grow + 8 * g) * DD + 4 * gq);
            *(uint4*)&S.Vs[grow + 8 * g][4 * gq] =
                make_uint4(f2tf(vv.x), f2tf(vv.y), f2tf(vv.z), f2tf(vv.w));
        }
        __syncthreads();  // K/V ready

        // ---- S = (Q*scale) @ K^T : per warp 16 x 32 ----
        float s[4][4];
#pragma unroll
        for (int nt = 0; nt < 4; nt++)
#pragma unroll
            for (int c = 0; c < 4; c++) s[nt][c] = 0.f;

#pragma unroll
        for (int kt = 0; kt < 16; kt++) {
            const int k0 = kt * 8;
            uint32_t a[4];
            a[0] = S.Qs[r0][k0 + tig];
            a[1] = S.Qs[r0 + 8][k0 + tig];
            a[2] = S.Qs[r0][k0 + tig + 4];
            a[3] = S.Qs[r0 + 8][k0 + tig + 4];
#pragma unroll
            for (int nt = 0; nt < 4; nt++) {
                int c = wn * 32 + nt * 8 + group;
                uint32_t bb[2] = {S.Ks[c][k0 + tig], S.Ks[c][k0 + tig + 4]};
                mma8(s[nt], a, bb);
            }
        }

        // ---- causal mask (diag tile only) ----
        if (jt == t_tile) {
            const int gr0 = tq0 + r0, gr1 = gr0 + 8;
#pragma unroll
            for (int nt = 0; nt < 4; nt++) {
                int gc = j0 + wn * 32 + nt * 8 + 2 * tig;
                if (gc > gr0) s[nt][0] = NEG_INF;
                if (gc + 1 > gr0) s[nt][1] = NEG_INF;
                if (gc > gr1) s[nt][2] = NEG_INF;
                if (gc + 1 > gr1) s[nt][3] = NEG_INF;
            }
        }

        // ---- partial row max over this warp's 32 cols ----
        float pm0 = s[0][0], pm1 = s[0][2];
#pragma unroll
        for (int nt = 0; nt < 4; nt++) {
            pm0 = fmaxf(pm0, fmaxf(s[nt][0], s[nt][1]));
            pm1 = fmaxf(pm1, fmaxf(s[nt][2], s[nt][3]));
        }
        pm0 = fmaxf(pm0, __shfl_xor_sync(0xffffffffu, pm0, 1));
        pm0 = fmaxf(pm0, __shfl_xor_sync(0xffffffffu, pm0, 2));
        pm1 = fmaxf(pm1, __shfl_xor_sync(0xffffffffu, pm1, 1));
        pm1 = fmaxf(pm1, __shfl_xor_sync(0xffffffffu, pm1, 2));
        if (tig == 0) {
            S.redm[r0][wn] = pm0;
            S.redm[r0 + 8][wn] = pm1;
        }
        __syncthreads();

        // ---- exp + partial sums + P store (tf32) ----
        const float mn0 = fmaxf(S.m_s[r0], fmaxf(S.redm[r0][0], S.redm[r0][1]));
        const float mn1 = fmaxf(S.m_s[r0 + 8], fmaxf(S.redm[r0 + 8][0], S.redm[r0 + 8][1]));
        float ps0 = 0.f, ps1 = 0.f;
#pragma unroll
        for (int nt = 0; nt < 4; nt++) {
            int c = wn * 32 + nt * 8 + 2 * tig;
            float e0 = __expf(s[nt][0] - mn0);
            float e1 = __expf(s[nt][1] - mn0);
            float e2 = __expf(s[nt][2] - mn1);
            float e3 = __expf(s[nt][3] - mn1);
            ps0 += e0 + e1;
            ps1 += e2 + e3;
            S.Ps[r0][c] = f2tf(e0);
            S.Ps[r0][c + 1] = f2tf(e1);
            S.Ps[r0 + 8][c] = f2tf(e2);
            S.Ps[r0 + 8][c + 1] = f2tf(e3);
        }
        ps0 += __shfl_xor_sync(0xffffffffu, ps0, 1);
        ps0 += __shfl_xor_sync(0xffffffffu, ps0, 2);
        ps1 += __shfl_xor_sync(0xffffffffu, ps1, 1);
        ps1 += __shfl_xor_sync(0xffffffffu, ps1, 2);
        if (tig == 0) {
            S.reds[r0][wn] = ps0;
            S.reds[r0 + 8][wn] = ps1;
        }
        __syncthreads();

        // ---- stats update ----
        if (tid < 64) {
            float mo = S.m_s[tid];
            float mn = fmaxf(mo, fmaxf(S.redm[tid][0], S.redm[tid][1]));
            float sc = __expf(mo - mn);
            S.sc_s[tid] = sc;
            S.l_s[tid] = S.l_s[tid] * sc + S.reds[tid][0] + S.reds[tid][1];
            S.m_s[tid] = mn;
        }
        __syncthreads();

        // ---- rescale O, then O += P @ V : per warp 16 x 64 ----
        {
            const float sc0 = S.sc_s[r0], sc1 = S.sc_s[r0 + 8];
#pragma unroll
            for (int nt = 0; nt < 8; nt++) {
                o[nt][0] *= sc0; o[nt][1] *= sc0;
                o[nt][2] *= sc1; o[nt][3] *= sc1;
            }
        }
#pragma unroll
        for (int kt = 0; kt < 8; kt++) {
            const int k0 = kt * 8;
            uint32_t a[4];
            a[0] = S.Ps[r0][k0 + tig];
            a[1] = S.Ps[r0 + 8][k0 + tig];
            a[2] = S.Ps[r0][k0 + tig + 4];
            a[3] = S.Ps[r0 + 8][k0 + tig + 4];
#pragma unroll
            for (int nt = 0; nt < 8; nt++) {
                int c = wn * 64 + nt * 8 + group;
                uint32_t bb[2] = {S.Vs[k0 + tig][c], S.Vs[k0 + tig + 4][c]};
                mma8(o[nt], a, bb);
            }
        }
    }

    // ---- normalize + write out ----
    const float inv0 = 1.0f / S.l_s[r0];
    const float inv1 = 1.0f / S.l_s[r0 + 8];
    float* O0 = out + ((size_t)b * TT + tq0 + r0) * DD;
    float* O1 = O0 + 8 * DD;
#pragma unroll
    for (int nt = 0; nt < 8; nt++) {
        int c = wn * 64 + nt * 8 + 2 * tig;
        *(float2*)(O0 + c) = make_float2(o[nt][0] * inv0, o[nt][1] * inv0);
        *(float2*)(O1 + c) = make_float2(o[nt][2] * inv1, o[nt][3] * inv1);
    }
}

// ---------------------------------------------------------------------------
extern "C" void kernel_launch(void* const* d_in, const int* in_sizes, int n_in,
                              void* d_out, int out_size) {
    const float* x  = (const float*)d_in[0];
    const float* Wk = (const float*)d_in[1];
    const float* Wq = (const float*)d_in[2];
    const float* Wv = (const float*)d_in[3];
    float* out = (float*)d_out;

    dim3 pgrid(128, 3);
    proj_kernel<<<pgrid, 256>>>(x, Wk, Wq, Wv);

    cudaFuncSetAttribute(attn_kernel, cudaFuncAttributeMaxDynamicSharedMemorySize,
                         (int)sizeof(AttnSmem));
    dim3 agrid(32, 8);
    attn_kernel<<<agrid, 256, sizeof(AttnSmem)>>>(out);
}

// round 7
// speedup vs baseline: 3.0498x; 1.2039x over previous
#include <cuda_runtime.h>
#include <cstdint>

#define BB 8
#define TT 2048
#define EE 1024
#define DD 128

// Scratch for projected Q/K/V (no cudaMalloc allowed -> __device__ globals)
__device__ float g_q[BB * TT * DD];
__device__ float g_k[BB * TT * DD];
__device__ float g_v[BB * TT * DD];

__device__ __forceinline__ uint32_t f2tf(float f) {
    uint32_t r;
    asm("cvt.rna.tf32.f32 %0, %1;" : "=r"(r) : "f"(f));
    return r;
}

// D += A*B, m16n8k8 tf32
__device__ __forceinline__ void mma8(float* d, const uint32_t* a, const uint32_t* b) {
    asm volatile(
        "mma.sync.aligned.m16n8k8.row.col.f32.tf32.tf32.f32 "
        "{%0,%1,%2,%3}, {%4,%5,%6,%7}, {%8,%9}, {%0,%1,%2,%3};"
        : "+f"(d[0]), "+f"(d[1]), "+f"(d[2]), "+f"(d[3])
        : "r"(a[0]), "r"(a[1]), "r"(a[2]), "r"(a[3]), "r"(b[0]), "r"(b[1]));
}

// ---------------------------------------------------------------------------
// Projection: X[16384,1024] @ W[1024,128], tf32 MMA. 128x128 tile, BK=32.
// 512 threads, 16 warps: wm = wid>>2 (32 rows), wn = wid&3 (32 cols).
// ---------------------------------------------------------------------------
__global__ __launch_bounds__(512) void proj_kernel(
    const float* __restrict__ X,
    const float* __restrict__ Wk,
    const float* __restrict__ Wq,
    const float* __restrict__ Wv) {
    __shared__ uint32_t As[128][36];   // [m][k]
    __shared__ uint32_t Bs[32][136];   // [k][n]

    const float* W;
    float* O;
    if (blockIdx.y == 0)      { W = Wk; O = g_k; }
    else if (blockIdx.y == 1) { W = Wq; O = g_q; }
    else                      { W = Wv; O = g_v; }

    const int tid = threadIdx.x;
    const int wid = tid >> 5, lane = tid & 31;
    const int group = lane >> 2, tig = lane & 3;
    const int wm = wid >> 2, wn = wid & 3;
    const int m0 = blockIdx.x * 128;

    const int xrow = tid >> 3, xq = tid & 7;     // rows xrow + 64g
    const int wrow = tid >> 5, wq = tid & 31;    // rows wrow + 16g

    float acc[2][4][4];
#pragma unroll
    for (int mt = 0; mt < 2; mt++)
#pragma unroll
        for (int nt = 0; nt < 4; nt++)
#pragma unroll
            for (int c = 0; c < 4; c++) acc[mt][nt][c] = 0.f;

    float4 xv[2], wv[2];
#pragma unroll
    for (int g = 0; g < 2; g++) {
        xv[g] = *(const float4*)(X + (size_t)(m0 + xrow + 64 * g) * EE + 4 * xq);
        wv[g] = *(const float4*)(W + (size_t)(wrow + 16 * g) * DD + 4 * wq);
    }

    for (int e0 = 0; e0 < EE; e0 += 32) {
#pragma unroll
        for (int g = 0; g < 2; g++) {
            *(uint4*)&As[xrow + 64 * g][4 * xq] =
                make_uint4(f2tf(xv[g].x), f2tf(xv[g].y), f2tf(xv[g].z), f2tf(xv[g].w));
            *(uint4*)&Bs[wrow + 16 * g][4 * wq] =
                make_uint4(f2tf(wv[g].x), f2tf(wv[g].y), f2tf(wv[g].z), f2tf(wv[g].w));
        }
        __syncthreads();

        if (e0 + 32 < EE) {
#pragma unroll
            for (int g = 0; g < 2; g++) {
                xv[g] = *(const float4*)(X + (size_t)(m0 + xrow + 64 * g) * EE + e0 + 32 + 4 * xq);
                wv[g] = *(const float4*)(W + (size_t)(e0 + 32 + wrow + 16 * g) * DD + 4 * wq);
            }
        }

#pragma unroll
        for (int kt = 0; kt < 4; kt++) {
            const int k0 = kt * 8;
            uint32_t a[2][4], b[4][2];
#pragma unroll
            for (int mt = 0; mt < 2; mt++) {
                int r = wm * 32 + mt * 16 + group;
                a[mt][0] = As[r][k0 + tig];
                a[mt][1] = As[r + 8][k0 + tig];
                a[mt][2] = As[r][k0 + tig + 4];
                a[mt][3] = As[r + 8][k0 + tig + 4];
            }
#pragma unroll
            for (int nt = 0; nt < 4; nt++) {
                int c = wn * 32 + nt * 8 + group;
                b[nt][0] = Bs[k0 + tig][c];
                b[nt][1] = Bs[k0 + tig + 4][c];
            }
#pragma unroll
            for (int mt = 0; mt < 2; mt++)
#pragma unroll
                for (int nt = 0; nt < 4; nt++) mma8(acc[mt][nt], a[mt], b[nt]);
        }
        __syncthreads();
    }

#pragma unroll
    for (int mt = 0; mt < 2; mt++) {
        int r = m0 + wm * 32 + mt * 16 + group;
#pragma unroll
        for (int nt = 0; nt < 4; nt++) {
            int c = wn * 32 + nt * 8 + 2 * tig;
            *(float2*)(O + (size_t)r * DD + c) = make_float2(acc[mt][nt][0], acc[mt][nt][1]);
            *(float2*)(O + (size_t)(r + 8) * DD + c) = make_float2(acc[mt][nt][2], acc[mt][nt][3]);
        }
    }
}

// ---------------------------------------------------------------------------
// Flash attention, causal, tf32 MMA. Br=Bc=64, 512 threads (16 warps).
// Warps: wm = wid>>2 (16 rows each), wn = wid&3 (16 S-cols / 32 O-cols).
// CTA blockIdx.x = pair p handles q-tiles {31-p, p}: 33 KV iters each -> one
// perfectly balanced wave of 128 CTAs. m/l stats live in registers
// (redundant per column-warp), so no serial stats step; 4 syncs per tile.
// ---------------------------------------------------------------------------
struct AttnSmem {
    uint32_t Qs[64][132];   // [row][d], pre-scaled
    uint32_t Ks[64][132];   // [key][d]
    uint32_t Vs[64][136];   // [key][d]
    uint32_t Ps[64][68];    // [row][key]
    float redm[64][4];      // partial row max per col-warp
    float reds[64][4];      // partial row sum per col-warp
};

__global__ __launch_bounds__(512) void attn_kernel(float* __restrict__ out) {
    extern __shared__ __align__(16) char smem_raw[];
    AttnSmem& S = *reinterpret_cast<AttnSmem*>(smem_raw);

    const int b = blockIdx.y;
    const int pair = blockIdx.x;   // 0..15
    const int tid = threadIdx.x;
    const int wid = tid >> 5, lane = tid & 31;
    const int group = lane >> 2, tig = lane & 3;
    const int wm = wid >> 2, wn = wid & 3;
    const int r0 = wm * 16 + group;               // local rows r0, r0+8
    const float SM_SCALE = 0.08838834764831845f;  // 1/sqrt(128)
    const float NEG_INF = __int_as_float(0xff800000);

    const int grow = tid >> 5, gq = tid & 31;     // tile loads: rows grow+16g

#pragma unroll
    for (int seg = 0; seg < 2; seg++) {
        const int qt = seg == 0 ? (31 - pair) : pair;
        const int tq0 = qt * 64;

        float o[4][4];
#pragma unroll
        for (int nt = 0; nt < 4; nt++)
#pragma unroll
            for (int c = 0; c < 4; c++) o[nt][c] = 0.f;
        float mr0 = NEG_INF, mr1 = NEG_INF, lr0 = 0.f, lr1 = 0.f;

        // Load Q tile (pre-scaled). Sync first: protect Qs reuse across segs.
        __syncthreads();
        const float* Qg = g_q + ((size_t)b * TT + tq0) * DD;
#pragma unroll
        for (int g = 0; g < 4; g++) {
            float4 qv = *(const float4*)(Qg + (size_t)(grow + 16 * g) * DD + 4 * gq);
            *(uint4*)&S.Qs[grow + 16 * g][4 * gq] =
                make_uint4(f2tf(qv.x * SM_SCALE), f2tf(qv.y * SM_SCALE),
                           f2tf(qv.z * SM_SCALE), f2tf(qv.w * SM_SCALE));
        }

        for (int jt = 0; jt <= qt; jt++) {
            const int j0 = jt * 64;
            const float* Kg = g_k + ((size_t)b * TT + j0) * DD;
            const float* Vg = g_v + ((size_t)b * TT + j0) * DD;

            // Prefetch K/V to registers (overlaps previous tile's PV MMAs)
            float4 kvv[4], vvv[4];
#pragma unroll
            for (int g = 0; g < 4; g++) {
                kvv[g] = *(const float4*)(Kg + (size_t)(grow + 16 * g) * DD + 4 * gq);
                vvv[g] = *(const float4*)(Vg + (size_t)(grow + 16 * g) * DD + 4 * gq);
            }
            __syncthreads();  // sync1: prev tile's Ks/Vs consumers done
#pragma unroll
            for (int g = 0; g < 4; g++) {
                *(uint4*)&S.Ks[grow + 16 * g][4 * gq] =
                    make_uint4(f2tf(kvv[g].x), f2tf(kvv[g].y), f2tf(kvv[g].z), f2tf(kvv[g].w));
                *(uint4*)&S.Vs[grow + 16 * g][4 * gq] =
                    make_uint4(f2tf(vvv[g].x), f2tf(vvv[g].y), f2tf(vvv[g].z), f2tf(vvv[g].w));
            }
            __syncthreads();  // sync2: K/V (and Q on jt==0) visible

            // ---- S = (Q*scale) @ K^T : per warp 16 x 16 ----
            float s[2][4];
#pragma unroll
            for (int nt = 0; nt < 2; nt++)
#pragma unroll
                for (int c = 0; c < 4; c++) s[nt][c] = 0.f;

#pragma unroll
            for (int kt = 0; kt < 16; kt++) {
                const int k0 = kt * 8;
                uint32_t a[4];
                a[0] = S.Qs[r0][k0 + tig];
                a[1] = S.Qs[r0 + 8][k0 + tig];
                a[2] = S.Qs[r0][k0 + tig + 4];
                a[3] = S.Qs[r0 + 8][k0 + tig + 4];
#pragma unroll
                for (int nt = 0; nt < 2; nt++) {
                    int c = wn * 16 + nt * 8 + group;
                    uint32_t bb[2] = {S.Ks[c][k0 + tig], S.Ks[c][k0 + tig + 4]};
                    mma8(s[nt], a, bb);
                }
            }

            // ---- causal mask (diag tile only) ----
            if (jt == qt) {
                const int gr0 = tq0 + r0, gr1 = gr0 + 8;
#pragma unroll
                for (int nt = 0; nt < 2; nt++) {
                    int gc = j0 + wn * 16 + nt * 8 + 2 * tig;
                    if (gc > gr0) s[nt][0] = NEG_INF;
                    if (gc + 1 > gr0) s[nt][1] = NEG_INF;
                    if (gc > gr1) s[nt][2] = NEG_INF;
                    if (gc + 1 > gr1) s[nt][3] = NEG_INF;
                }
            }

            // ---- partial row max over this warp's 16 cols ----
            float pm0 = s[0][0], pm1 = s[0][2];
#pragma unroll
            for (int nt = 0; nt < 2; nt++) {
                pm0 = fmaxf(pm0, fmaxf(s[nt][0], s[nt][1]));
                pm1 = fmaxf(pm1, fmaxf(s[nt][2], s[nt][3]));
            }
            pm0 = fmaxf(pm0, __shfl_xor_sync(0xffffffffu, pm0, 1));
            pm0 = fmaxf(pm0, __shfl_xor_sync(0xffffffffu, pm0, 2));
            pm1 = fmaxf(pm1, __shfl_xor_sync(0xffffffffu, pm1, 1));
            pm1 = fmaxf(pm1, __shfl_xor_sync(0xffffffffu, pm1, 2));
            if (tig == 0) {
                S.redm[r0][wn] = pm0;
                S.redm[r0 + 8][wn] = pm1;
            }
            __syncthreads();  // sync3: all partial maxes visible

            // ---- new row max, exp, P store, partial sums ----
            const float mn0 = fmaxf(fmaxf(mr0, fmaxf(S.redm[r0][0], S.redm[r0][1])),
                                    fmaxf(S.redm[r0][2], S.redm[r0][3]));
            const float mn1 = fmaxf(fmaxf(mr1, fmaxf(S.redm[r0 + 8][0], S.redm[r0 + 8][1])),
                                    fmaxf(S.redm[r0 + 8][2], S.redm[r0 + 8][3]));
            float ps0 = 0.f, ps1 = 0.f;
#pragma unroll
            for (int nt = 0; nt < 2; nt++) {
                int c = wn * 16 + nt * 8 + 2 * tig;
                float e0 = __expf(s[nt][0] - mn0);
                float e1 = __expf(s[nt][1] - mn0);
                float e2 = __expf(s[nt][2] - mn1);
                float e3 = __expf(s[nt][3] - mn1);
                ps0 += e0 + e1;
                ps1 += e2 + e3;
                S.Ps[r0][c] = f2tf(e0);
                S.Ps[r0][c + 1] = f2tf(e1);
                S.Ps[r0 + 8][c] = f2tf(e2);
                S.Ps[r0 + 8][c + 1] = f2tf(e3);
            }
            ps0 += __shfl_xor_sync(0xffffffffu, ps0, 1);
            ps0 += __shfl_xor_sync(0xffffffffu, ps0, 2);
            ps1 += __shfl_xor_sync(0xffffffffu, ps1, 1);
            ps1 += __shfl_xor_sync(0xffffffffu, ps1, 2);
            if (tig == 0) {
                S.reds[r0][wn] = ps0;
                S.reds[r0 + 8][wn] = ps1;
            }
            __syncthreads();  // sync4: P and partial sums visible

            // ---- stats update in registers (redundant across wn warps) ----
            const float sc0 = __expf(mr0 - mn0);
            const float sc1 = __expf(mr1 - mn1);
            mr0 = mn0;
            mr1 = mn1;
            lr0 = lr0 * sc0 + S.reds[r0][0] + S.reds[r0][1] + S.reds[r0][2] + S.reds[r0][3];
            lr1 = lr1 * sc1 + S.reds[r0 + 8][0] + S.reds[r0 + 8][1] + S.reds[r0 + 8][2] + S.reds[r0 + 8][3];

            // ---- rescale O, then O += P @ V : per warp 16 x 32 ----
#pragma unroll
            for (int nt = 0; nt < 4; nt++) {
                o[nt][0] *= sc0; o[nt][1] *= sc0;
                o[nt][2] *= sc1; o[nt][3] *= sc1;
            }
#pragma unroll
            for (int kt = 0; kt < 8; kt++) {
                const int k0 = kt * 8;
                uint32_t a[4];
                a[0] = S.Ps[r0][k0 + tig];
                a[1] = S.Ps[r0 + 8][k0 + tig];
                a[2] = S.Ps[r0][k0 + tig + 4];
                a[3] = S.Ps[r0 + 8][k0 + tig + 4];
#pragma unroll
                for (int nt = 0; nt < 4; nt++) {
                    int c = wn * 32 + nt * 8 + group;
                    uint32_t bb[2] = {S.Vs[k0 + tig][c], S.Vs[k0 + tig + 4][c]};
                    mma8(o[nt], a, bb);
                }
            }
        }

        // ---- normalize + write out (l already in registers, all warps) ----
        const float inv0 = 1.0f / lr0;
        const float inv1 = 1.0f / lr1;
        float* O0 = out + ((size_t)b * TT + tq0 + r0) * DD;
        float* O1 = O0 + 8 * DD;
#pragma unroll
        for (int nt = 0; nt < 4; nt++) {
            int c = wn * 32 + nt * 8 + 2 * tig;
            *(float2*)(O0 + c) = make_float2(o[nt][0] * inv0, o[nt][1] * inv0);
            *(float2*)(O1 + c) = make_float2(o[nt][2] * inv1, o[nt][3] * inv1);
        }
    }
}

// ---------------------------------------------------------------------------
extern "C" void kernel_launch(void* const* d_in, const int* in_sizes, int n_in,
                              void* d_out, int out_size) {
    const float* x  = (const float*)d_in[0];
    const float* Wk = (const float*)d_in[1];
    const float* Wq = (const float*)d_in[2];
    const float* Wv = (const float*)d_in[3];
    float* out = (float*)d_out;

    dim3 pgrid(128, 3);
    proj_kernel<<<pgrid, 512>>>(x, Wk, Wq, Wv);

    cudaFuncSetAttribute(attn_kernel, cudaFuncAttributeMaxDynamicSharedMemorySize,
                         (int)sizeof(AttnSmem));
    dim3 agrid(16, 8);  // 16 balanced tile-pairs x 8 batch = 128 CTAs
    attn_kernel<<<agrid, 512, sizeof(AttnSmem)>>>(out);
}